// round 14
// baseline (speedup 1.0000x reference)
#include <cuda_runtime.h>
#include <math_constants.h>

#define B    32
#define T    336
#define C    7
#define NSH  5
#define NG   4
#define NF   140            // 4 groups * 5 * 7
#define OUTC 10
#define NWORKBLK (B * C * NSH)      // 1120 worker blocks (bc, nn), 6 warps each
#define NHEAD    21                 // 20 dot blocks + 1 loss block
#define NTHR     192

// offsets in d_out (floats): out[320] | dists[4480] | probs[4480] | loss[1]
#define OFF_OUT   0
#define OFF_DIST  320
#define OFF_PROB  (320 + B*NF)
#define OFF_LOSS  (320 + 2*B*NF)

#define SXN 352            // padded row length (floats, zero tail)

__device__ int g_ctr  = 0;   // worker blocks completed
__device__ int g_ctr2 = 0;   // head blocks completed

// ---------------------------------------------------------------------------
// Run M contiguous passes (p0 .. p0+M-1) of the L-sweep. Pass p covers window
// pairs with base beta = ll + 32p (clamped; duplicates are min-safe).
// float2 rolling body: per h per m: 1 LDS.64 + 8 FADD; w broadcast LDS.64.
// Warp-reduces its partial min and atomicMin's it into smin[gslot].
// ---------------------------------------------------------------------------
template<int L, int M>
__device__ __forceinline__ void run_pass(const float* __restrict__ sx,
                                         const float* __restrict__ swg,
                                         int ll, int p0,
                                         unsigned* __restrict__ sminp) {
    constexpr int TW      = T - L + 1;
    constexpr int BETAMAX = (TW - 1) / 2;
    constexpr int H       = L / 2;

    const float2* sx2 = reinterpret_cast<const float2*>(sx);
    const float2* sw2 = reinterpret_cast<const float2*>(swg);

    int    beta[M];
    float  a0[M], a1[M];
    float2 cur[M];
    #pragma unroll
    for (int m = 0; m < M; m++) {
        int bt = ll + 32 * (p0 + m);
        if (bt > BETAMAX) bt = BETAMAX;            // duplicate work, min-safe
        beta[m] = bt;
        a0[m] = 0.f;
        a1[m] = (2 * bt + 1 < TW) ? 0.f : CUDART_INF_F;
        cur[m] = sx2[bt];
    }

    #pragma unroll 2
    for (int h = 0; h < H; h++) {
        const float2 w = sw2[h];                    // broadcast LDS.64
        #pragma unroll
        for (int m = 0; m < M; m++) {
            const float2 nxt = sx2[beta[m] + h + 1]; // stride-1 lanes, no conflict
            a0[m] += fabsf(cur[m].x - w.x);
            a1[m] += fabsf(cur[m].y - w.x);
            a0[m] += fabsf(cur[m].y - w.y);
            a1[m] += fabsf(nxt.x    - w.y);
            cur[m] = nxt;
        }
    }
    if (L & 1) {                                    // final step l = L-1
        const float w = swg[L - 1];
        #pragma unroll
        for (int m = 0; m < M; m++) {
            a0[m] += fabsf(cur[m].x - w);
            a1[m] += fabsf(cur[m].y - w);
        }
    }

    float mn = CUDART_INF_F;
    #pragma unroll
    for (int m = 0; m < M; m++) mn = fminf(mn, fminf(a0[m], a1[m]));
    #pragma unroll
    for (int o = 16; o > 0; o >>= 1)
        mn = fminf(mn, __shfl_xor_sync(0xffffffffu, mn, o));
    if (ll == 0) atomicMin(sminp, __float_as_uint(mn));   // d>=0: bits monotone
}

// sw row offsets (even): g0@0(34) g1@36(68) g2@104(101) g3@208(168)
#define SW_TOT 376

__constant__ float c_invL[4] = { 1.f/34.f, 1.f/68.f, 1.f/101.f, 1.f/168.f };

// ---------------------------------------------------------------------------
// Single launch. grid.x = 1120 workers + 21 heads, 192 threads (6 warps).
// Worker block = one (bc, nn); 17 passes in 6 BALANCED work items (unit=pass*L):
//   wk0: g3p0 + g1p0            (236)
//   wk1: g3p1 + g1p1            (236)
//   wk2: g3p2 + g1p2            (236)
//   wk3: g2p0-1 + g0p0          (236)
//   wk4: g2p2-3 + g0p1          (236)
//   wk5: g1p3-4 + g0p2-4        (238)
// Item-to-warp rotated by bid so same-cost-but-different-shape items mix.
// ---------------------------------------------------------------------------
__global__ __launch_bounds__(NTHR, 8) void fused_kernel(
        const float* __restrict__ x,
        const float* __restrict__ w0,
        const float* __restrict__ w1,
        const float* __restrict__ w2,
        const float* __restrict__ w3,
        const float* __restrict__ Wout,
        float* __restrict__ d_out) {
    const int bid = blockIdx.x;
    const int tid = threadIdx.x;          // 192

    if (bid < NWORKBLK) {
        // ================= WORKER =================
        const int nn = bid % NSH;
        const int bc = bid / NSH;
        const int b  = bc / C;
        const int ch = bc % C;
        const int wp = tid >> 5;             // warp 0..5
        const int ll = tid & 31;

        __shared__ __align__(16) float sx[SXN];
        __shared__ __align__(16) float sw[SW_TOT];
        __shared__ float red[12];
        __shared__ unsigned smin[4];

        // ---- normalization: one pass sum + sumsq over the (b,ch) row ----
        const float* xrow = x + (size_t)b * T * C + ch;   // stride C over t
        float vals[2];
        float s = 0.f, ss = 0.f;
        #pragma unroll
        for (int i = 0; i < 2; i++) {
            int t = tid + i * NTHR;
            float v = (t < T) ? xrow[(size_t)t * C] : 0.f;
            vals[i] = v;
            s += v;
            ss += v * v;
        }
        #pragma unroll
        for (int o = 16; o > 0; o >>= 1) {
            s  += __shfl_xor_sync(0xffffffffu, s, o);
            ss += __shfl_xor_sync(0xffffffffu, ss, o);
        }
        if (ll == 0) { red[wp] = s; red[6 + wp] = ss; }
        if (tid < 4) smin[tid] = 0x7f800000u;   // +inf bits

        // ---- warps 0-3 load shapelet row of group wp ----
        if (wp < 4) {
            int L, goff;
            const float* wg;
            switch (wp) {
                case 0:  L = 34;  goff = 0;   wg = w0; break;
                case 1:  L = 68;  goff = 36;  wg = w1; break;
                case 2:  L = 101; goff = 104; wg = w2; break;
                default: L = 168; goff = 208; wg = w3; break;
            }
            const float* wrow = wg + (size_t)(nn * C + ch) * L;
            for (int i = ll; i < L; i += 32) sw[goff + i] = wrow[i];
        }

        __syncthreads();
        float stot = 0.f, sstot = 0.f;
        #pragma unroll
        for (int i = 0; i < 6; i++) { stot += red[i]; sstot += red[6 + i]; }
        const float mu  = stot * (1.0f / (float)T);
        const float var = (sstot - (float)T * mu * mu) * (1.0f / (float)(T - 1));
        const float inv = 1.0f / (sqrtf(fmaxf(var, 0.f)) + 1e-8f);

        #pragma unroll
        for (int i = 0; i < 2; i++) {
            int t = tid + i * NTHR;
            if (t < T) sx[t] = (vals[i] - mu) * inv;
        }
        if (tid < SXN - T) sx[T + tid] = 0.f;   // zero pad (only +inf pairs read)
        __syncthreads();

        // ---- 6 balanced warp work items, rotated across blocks ----
        int wk = wp + (bid % 6);
        if (wk >= 6) wk -= 6;
        switch (wk) {
            case 0:
                run_pass<168, 1>(sx, sw + 208, ll, 0, &smin[3]);
                run_pass<68,  1>(sx, sw + 36,  ll, 0, &smin[1]);
                break;
            case 1:
                run_pass<168, 1>(sx, sw + 208, ll, 1, &smin[3]);
                run_pass<68,  1>(sx, sw + 36,  ll, 1, &smin[1]);
                break;
            case 2:
                run_pass<168, 1>(sx, sw + 208, ll, 2, &smin[3]);
                run_pass<68,  1>(sx, sw + 36,  ll, 2, &smin[1]);
                break;
            case 3:
                run_pass<101, 2>(sx, sw + 104, ll, 0, &smin[2]);
                run_pass<34,  1>(sx, sw + 0,   ll, 0, &smin[0]);
                break;
            case 4:
                run_pass<101, 2>(sx, sw + 104, ll, 2, &smin[2]);
                run_pass<34,  1>(sx, sw + 0,   ll, 1, &smin[0]);
                break;
            default:
                run_pass<68,  2>(sx, sw + 36,  ll, 3, &smin[1]);
                run_pass<34,  3>(sx, sw + 0,   ll, 2, &smin[0]);
                break;
        }
        __syncthreads();

        if (tid < 4) {                      // one thread per g writes results
            const float dmin = __uint_as_float(smin[tid]) * c_invL[tid];
            const int idx = b * NF + tid * (NSH * C) + nn * C + ch;
            d_out[OFF_DIST + idx] = dmin;
            d_out[OFF_PROB + idx] = expf(-dmin * dmin);   // EPS_GATE = 1
        }
        __syncthreads();
        if (tid == 0) {
            __threadfence();
            atomicAdd(&g_ctr, 1);           // publish this block's 4 results
        }
    } else {
        // ================= HEAD =================
        const int h = bid - NWORKBLK;    // 0..20

        if (tid == 0) {
            while (atomicAdd(&g_ctr, 0) < NWORKBLK) __nanosleep(64);
        }
        __syncthreads();
        __threadfence();                  // acquire published probs

        if (h < 20) {
            // 16 dots per block; 6 warps strided over them
            const int wp = tid >> 5;
            const int ln = tid & 31;
            const float* probs = d_out + OFF_PROB;
            for (int di = wp; di < 16; di += 6) {
                const int dot = h * 16 + di;             // < 320
                const int bb = dot / OUTC;
                const int o  = dot % OUTC;
                const float* p  = probs + bb * NF;
                const float* wv = Wout + o * NF;
                float v = 0.f;
                #pragma unroll
                for (int f = ln; f < NF; f += 32) v += p[f] * wv[f];
                #pragma unroll
                for (int off = 16; off > 0; off >>= 1)
                    v += __shfl_xor_sync(0xffffffffu, v, off);
                if (ln == 0) d_out[OFF_OUT + dot] = v;
            }
        } else {
            // loss = 0.1 * mean|Wout|
            __shared__ float sred[6];
            float v = 0.f;
            for (int i = tid; i < OUTC * NF; i += NTHR) v += fabsf(Wout[i]);
            #pragma unroll
            for (int off = 16; off > 0; off >>= 1)
                v += __shfl_xor_sync(0xffffffffu, v, off);
            if ((tid & 31) == 0) sred[tid >> 5] = v;
            __syncthreads();
            if (tid == 0) {
                float tot = 0.f;
                #pragma unroll
                for (int i = 0; i < 6; i++) tot += sred[i];
                d_out[OFF_LOSS] = 0.1f * tot / (float)(OUTC * NF);
            }
        }

        __syncthreads();
        if (tid == 0) {
            int v = atomicAdd(&g_ctr2, 1);
            if (v == NHEAD - 1) {
                // last head block resets counters for the next graph replay
                atomicExch(&g_ctr, 0);
                atomicExch(&g_ctr2, 0);
            }
        }
    }
}

// ---------------------------------------------------------------------------
extern "C" void kernel_launch(void* const* d_in, const int* in_sizes, int n_in,
                              void* d_out, int out_size) {
    const float* x    = (const float*)d_in[0];
    const float* w0   = (const float*)d_in[1];
    const float* w1   = (const float*)d_in[2];
    const float* w2   = (const float*)d_in[3];
    const float* w3   = (const float*)d_in[4];
    const float* Wout = (const float*)d_in[5];
    float* out = (float*)d_out;

    fused_kernel<<<NWORKBLK + NHEAD, NTHR>>>(x, w0, w1, w2, w3, Wout, out);
}

// round 15
// speedup vs baseline: 1.1235x; 1.1235x over previous
#include <cuda_runtime.h>
#include <cuda_fp16.h>
#include <math_constants.h>

#define B    32
#define T    336
#define C    7
#define NSH  5
#define NG   4
#define NF   140            // 4 groups * 5 * 7
#define OUTC 10
#define NWORKBLK (B * C * NSH)      // 1120 worker blocks (bc, nn), 4 warps
#define NHEAD    21                 // 20 dot blocks + 1 loss block

// offsets in d_out (floats): out[320] | dists[4480] | probs[4480] | loss[1]
#define OFF_OUT   0
#define OFF_DIST  320
#define OFF_PROB  (320 + B*NF)
#define OFF_LOSS  (320 + 2*B*NF)

#define SXN   356          // fp32 staging, zero-padded
#define PAIRN 176          // half2 pair arrays length
// swh offsets (half2 entries, even): g0@0(34) g1@64(68) g2@160(101) g3@288(168)
#define SWH_TOT 456

__device__ int g_ctr  = 0;   // worker blocks completed
__device__ int g_ctr2 = 0;   // head blocks completed

__constant__ float c_invL[4] = { 1.f/34.f, 1.f/68.f, 1.f/101.f, 1.f/168.f };

// ---------------------------------------------------------------------------
// fp16 quad sliding-min. Lane owns window quad j = 4*gamma, gamma = ll+32*(p0+m)
// (clamped; duplicates min-safe). A01 packs windows (j,j+1), A23 (j+2,j+3).
// Per h (2 l-steps): 1 broadcast LDS.64 (w pair) + 2 rolling LDS.32 + 8 H-ops
// for 8 window-elements. half2 chunks (16 l-steps) flushed into fp32.
// Invalid windows start at +inf(half) and stay inf through flushes.
// ---------------------------------------------------------------------------
template<int L, int M>
__device__ __forceinline__ void run_fp16(const __half2* __restrict__ she,
                                         const __half2* __restrict__ sho,
                                         const __half2* __restrict__ swh,
                                         int ll, int p0,
                                         unsigned* __restrict__ sminp) {
    constexpr int TW   = T - L + 1;
    constexpr int GMAX = (TW - 1) / 4;
    constexpr int H    = L / 2;
    constexpr int NB   = H / 8;
    constexpr int HREM = H - NB * 8;

    const __half hz   = __ushort_as_half((unsigned short)0x0000);
    const __half hinf = __ushort_as_half((unsigned short)0x7C00);

    int     e[M];
    __half2 A01[M], A23[M], I01[M], I23[M], E0[M], E1[M], O0[M], O1[M];
    float2  f01[M], f23[M];
    #pragma unroll
    for (int m = 0; m < M; m++) {
        int gt = ll + 32 * (p0 + m);
        if (gt > GMAX) gt = GMAX;               // duplicate work, min-safe
        const int j = 4 * gt;
        I01[m] = __halves2half2(hz, (j + 1 < TW) ? hz : hinf);
        I23[m] = __halves2half2((j + 2 < TW) ? hz : hinf,
                                (j + 3 < TW) ? hz : hinf);
        A01[m] = I01[m]; A23[m] = I23[m];
        f01[m] = make_float2(0.f, 0.f);
        f23[m] = make_float2(0.f, 0.f);
        e[m] = 2 * gt;
        E0[m] = she[e[m]]; E1[m] = she[e[m] + 1];
        O0[m] = sho[e[m]]; O1[m] = sho[e[m] + 1];
    }

    int h = 0;
    #pragma unroll 1
    for (int hb = 0; hb < NB; hb++) {
        #pragma unroll
        for (int hh = 0; hh < 8; hh++) {
            const uint2 wv = *reinterpret_cast<const uint2*>(swh + 2 * (h + hh));
            const __half2 w0 = *reinterpret_cast<const __half2*>(&wv.x);
            const __half2 w1 = *reinterpret_cast<const __half2*>(&wv.y);
            #pragma unroll
            for (int m = 0; m < M; m++) {
                A01[m] = __hadd2(A01[m], __habs2(__hsub2(E0[m], w0)));
                A23[m] = __hadd2(A23[m], __habs2(__hsub2(E1[m], w0)));
                A01[m] = __hadd2(A01[m], __habs2(__hsub2(O0[m], w1)));
                A23[m] = __hadd2(A23[m], __habs2(__hsub2(O1[m], w1)));
                const int idx = e[m] + h + hh + 2;
                E0[m] = E1[m]; E1[m] = she[idx];
                O0[m] = O1[m]; O1[m] = sho[idx];
            }
        }
        h += 8;
        #pragma unroll
        for (int m = 0; m < M; m++) {           // chunk flush to fp32
            float2 t = __half22float2(A01[m]); f01[m].x += t.x; f01[m].y += t.y;
            t = __half22float2(A23[m]);        f23[m].x += t.x; f23[m].y += t.y;
            A01[m] = I01[m]; A23[m] = I23[m];
        }
    }
    #pragma unroll
    for (int hh = 0; hh < HREM; hh++) {         // tail h-steps (< 8)
        const uint2 wv = *reinterpret_cast<const uint2*>(swh + 2 * (h + hh));
        const __half2 w0 = *reinterpret_cast<const __half2*>(&wv.x);
        const __half2 w1 = *reinterpret_cast<const __half2*>(&wv.y);
        #pragma unroll
        for (int m = 0; m < M; m++) {
            A01[m] = __hadd2(A01[m], __habs2(__hsub2(E0[m], w0)));
            A23[m] = __hadd2(A23[m], __habs2(__hsub2(E1[m], w0)));
            A01[m] = __hadd2(A01[m], __habs2(__hsub2(O0[m], w1)));
            A23[m] = __hadd2(A23[m], __habs2(__hsub2(O1[m], w1)));
            const int idx = e[m] + h + hh + 2;
            E0[m] = E1[m]; E1[m] = she[idx];
            O0[m] = O1[m]; O1[m] = sho[idx];
        }
    }
    if (L & 1) {                                // last even step l = L-1
        const __half2 w0 = swh[L - 1];
        #pragma unroll
        for (int m = 0; m < M; m++) {
            A01[m] = __hadd2(A01[m], __habs2(__hsub2(E0[m], w0)));
            A23[m] = __hadd2(A23[m], __habs2(__hsub2(E1[m], w0)));
        }
    }

    float mn = CUDART_INF_F;
    #pragma unroll
    for (int m = 0; m < M; m++) {               // final flush + lane min
        float2 t = __half22float2(A01[m]); f01[m].x += t.x; f01[m].y += t.y;
        t = __half22float2(A23[m]);        f23[m].x += t.x; f23[m].y += t.y;
        mn = fminf(mn, fminf(fminf(f01[m].x, f01[m].y),
                             fminf(f23[m].x, f23[m].y)));
    }
    #pragma unroll
    for (int o = 16; o > 0; o >>= 1)
        mn = fminf(mn, __shfl_xor_sync(0xffffffffu, mn, o));
    if (ll == 0) atomicMin(sminp, __float_as_uint(mn));   // d>=0: bits monotone
}

// ---------------------------------------------------------------------------
// Single launch. grid.x = 1120 workers + 21 heads, 128 threads (4 warps).
// Work items (h-units): wk0: g3p0+g0p0 (101) | wk1: g3p1+g0p1-2 (118)
//                       wk2: g2p0-1 (100)    | wk3: g1p0-2 (102)
// ---------------------------------------------------------------------------
__global__ __launch_bounds__(128, 8) void fused_kernel(
        const float* __restrict__ x,
        const float* __restrict__ w0,
        const float* __restrict__ w1,
        const float* __restrict__ w2,
        const float* __restrict__ w3,
        const float* __restrict__ Wout,
        float* __restrict__ d_out) {
    const int bid = blockIdx.x;
    const int tid = threadIdx.x;          // 128

    if (bid < NWORKBLK) {
        // ================= WORKER =================
        const int nn = bid % NSH;
        const int bc = bid / NSH;
        const int b  = bc / C;
        const int ch = bc % C;
        const int wp = tid >> 5;             // warp 0..3
        const int ll = tid & 31;

        __shared__ __align__(16) float   sxf[SXN];
        __shared__ __align__(16) __half2 she[PAIRN];
        __shared__ __align__(16) __half2 sho[PAIRN];
        __shared__ __align__(16) __half2 swh[SWH_TOT];
        __shared__ float red[8];
        __shared__ unsigned smin[4];

        // ---- normalization: one pass sum + sumsq over the (b,ch) row ----
        const float* xrow = x + (size_t)b * T * C + ch;   // stride C over t
        float vals[3];
        float s = 0.f, ss = 0.f;
        #pragma unroll
        for (int i = 0; i < 3; i++) {
            int t = tid + i * 128;
            float v = (t < T) ? xrow[(size_t)t * C] : 0.f;
            vals[i] = v;
            s += v;
            ss += v * v;
        }
        #pragma unroll
        for (int o = 16; o > 0; o >>= 1) {
            s  += __shfl_xor_sync(0xffffffffu, s, o);
            ss += __shfl_xor_sync(0xffffffffu, ss, o);
        }
        if (ll == 0) { red[wp] = s; red[4 + wp] = ss; }
        if (tid < 4) smin[tid] = 0x7f800000u;   // +inf bits

        // ---- warp wp converts+stores shapelet row of group wp ----
        {
            int L, goff;
            const float* wg;
            switch (wp) {
                case 0:  L = 34;  goff = 0;   wg = w0; break;
                case 1:  L = 68;  goff = 64;  wg = w1; break;
                case 2:  L = 101; goff = 160; wg = w2; break;
                default: L = 168; goff = 288; wg = w3; break;
            }
            const float* wrow = wg + (size_t)(nn * C + ch) * L;
            for (int i = ll; i < L; i += 32)
                swh[goff + i] = __float2half2_rn(wrow[i]);
        }

        __syncthreads();
        const float stot  = red[0] + red[1] + red[2] + red[3];
        const float sstot = red[4] + red[5] + red[6] + red[7];
        const float mu  = stot * (1.0f / (float)T);
        const float var = (sstot - (float)T * mu * mu) * (1.0f / (float)(T - 1));
        const float inv = 1.0f / (sqrtf(fmaxf(var, 0.f)) + 1e-8f);

        #pragma unroll
        for (int i = 0; i < 3; i++) {
            int t = tid + i * 128;
            if (t < T) sxf[t] = (vals[i] - mu) * inv;
        }
        for (int i = T + tid; i < SXN; i += 128) sxf[i] = 0.f;  // zero pads
        __syncthreads();

        // ---- build fp16 pair arrays ----
        for (int i = tid; i < PAIRN; i += 128) {
            she[i] = __floats2half2_rn(sxf[2 * i],     sxf[2 * i + 1]);
            sho[i] = __floats2half2_rn(sxf[2 * i + 1], sxf[2 * i + 2]);
        }
        __syncthreads();

        // ---- balanced warp work items, rotated across blocks ----
        const int wk = (wp + bid) & 3;
        switch (wk) {
            case 0:
                run_fp16<168, 1>(she, sho, swh + 288, ll, 0, &smin[3]);
                run_fp16<34,  1>(she, sho, swh + 0,   ll, 0, &smin[0]);
                break;
            case 1:
                run_fp16<168, 1>(she, sho, swh + 288, ll, 1, &smin[3]);
                run_fp16<34,  2>(she, sho, swh + 0,   ll, 1, &smin[0]);
                break;
            case 2:
                run_fp16<101, 2>(she, sho, swh + 160, ll, 0, &smin[2]);
                break;
            default:
                run_fp16<68,  3>(she, sho, swh + 64,  ll, 0, &smin[1]);
                break;
        }
        __syncthreads();

        if (tid < 4) {                      // one thread per g writes results
            const float dmin = __uint_as_float(smin[tid]) * c_invL[tid];
            const int idx = b * NF + tid * (NSH * C) + nn * C + ch;
            d_out[OFF_DIST + idx] = dmin;
            d_out[OFF_PROB + idx] = expf(-dmin * dmin);   // EPS_GATE = 1
        }
        __syncthreads();
        if (tid == 0) {
            __threadfence();
            atomicAdd(&g_ctr, 1);           // publish this block's 4 results
        }
    } else {
        // ================= HEAD =================
        const int h = bid - NWORKBLK;    // 0..20

        if (tid == 0) {
            while (atomicAdd(&g_ctr, 0) < NWORKBLK) __nanosleep(64);
        }
        __syncthreads();
        __threadfence();                  // acquire published probs

        if (h < 20) {
            // 16 dots per block; warp wp does 4 dots
            const int wp = tid >> 5;
            const int ln = tid & 31;
            const float* probs = d_out + OFF_PROB;
            #pragma unroll
            for (int d = 0; d < 4; d++) {
                const int dot = h * 16 + wp * 4 + d;     // < 320
                const int bb = dot / OUTC;
                const int o  = dot % OUTC;
                const float* p  = probs + bb * NF;
                const float* wv = Wout + o * NF;
                float v = 0.f;
                #pragma unroll
                for (int f = ln; f < NF; f += 32) v += p[f] * wv[f];
                #pragma unroll
                for (int off = 16; off > 0; off >>= 1)
                    v += __shfl_xor_sync(0xffffffffu, v, off);
                if (ln == 0) d_out[OFF_OUT + dot] = v;
            }
        } else {
            // loss = 0.1 * mean|Wout|
            __shared__ float sred[4];
            float v = 0.f;
            #pragma unroll
            for (int i = tid; i < OUTC * NF; i += 128) v += fabsf(Wout[i]);
            #pragma unroll
            for (int off = 16; off > 0; off >>= 1)
                v += __shfl_xor_sync(0xffffffffu, v, off);
            if ((tid & 31) == 0) sred[tid >> 5] = v;
            __syncthreads();
            if (tid == 0) {
                float tot = sred[0] + sred[1] + sred[2] + sred[3];
                d_out[OFF_LOSS] = 0.1f * tot / (float)(OUTC * NF);
            }
        }

        __syncthreads();
        if (tid == 0) {
            int v = atomicAdd(&g_ctr2, 1);
            if (v == NHEAD - 1) {
                // last head block resets counters for the next graph replay
                atomicExch(&g_ctr, 0);
                atomicExch(&g_ctr2, 0);
            }
        }
    }
}

// ---------------------------------------------------------------------------
extern "C" void kernel_launch(void* const* d_in, const int* in_sizes, int n_in,
                              void* d_out, int out_size) {
    const float* x    = (const float*)d_in[0];
    const float* w0   = (const float*)d_in[1];
    const float* w1   = (const float*)d_in[2];
    const float* w2   = (const float*)d_in[3];
    const float* w3   = (const float*)d_in[4];
    const float* Wout = (const float*)d_in[5];
    float* out = (float*)d_out;

    fused_kernel<<<NWORKBLK + NHEAD, 128>>>(x, w0, w1, w2, w3, Wout, out);
}

// round 16
// speedup vs baseline: 1.2576x; 1.1193x over previous
#include <cuda_runtime.h>
#include <cuda_fp16.h>
#include <math_constants.h>

#define B    32
#define T    336
#define C    7
#define NSH  5
#define NG   4
#define NF   140            // 4 groups * 5 * 7
#define OUTC 10
#define NWORKBLK (B * C * NSH)      // 1120 worker blocks (bc, nn), 4 warps
#define NHEAD    21                 // 20 dot blocks + 1 loss block

// offsets in d_out (floats): out[320] | dists[4480] | probs[4480] | loss[1]
#define OFF_OUT   0
#define OFF_DIST  320
#define OFF_PROB  (320 + B*NF)
#define OFF_LOSS  (320 + 2*B*NF)

#define SXN   356          // fp32 staging, zero-padded
#define PAIRN 176          // half2 pair arrays length
// swh offsets (half2 entries, even): g0@0(34) g1@64(68) g2@160(101) g3@288(168)
#define SWH_TOT 456

__device__ int g_ctr  = 0;   // worker blocks completed
__device__ int g_ctr2 = 0;   // head blocks completed

__constant__ float c_invL[4] = { 1.f/34.f, 1.f/68.f, 1.f/101.f, 1.f/168.f };

// ---------------------------------------------------------------------------
// Wide fp16 sliding-min: lane owns W = 2*NA consecutive windows, base
// j = W*ll (clamped even). Acc n (half2) covers windows (j+2n, j+2n+1):
//   l=2h   -> pair she[e+n+h]      l=2h+1 -> pair sho[e+n+h]
// Rolling buffer E[0..NA], O[0..NA]: per h-step exactly 1 she + 1 sho load
// feeds all NA accumulators (6*NA H-ops) -> high ILP, minimal LDS.
// half2 chunks (16 l-steps) flushed to fp32. Invalid windows start at +inf.
// ---------------------------------------------------------------------------
template<int L, int NA>
__device__ __forceinline__ void run_wide(const __half2* __restrict__ she,
                                         const __half2* __restrict__ sho,
                                         const __half2* __restrict__ swh,
                                         int ll,
                                         unsigned* __restrict__ sminp) {
    constexpr int TW   = T - L + 1;
    constexpr int W    = 2 * NA;
    constexpr int JC   = (TW - W + 2) & ~1;   // even clamp base, reaches TW-1
    constexpr int H    = L / 2;
    constexpr int NB   = H / 8;
    constexpr int HREM = H - NB * 8;

    const __half hz   = __ushort_as_half((unsigned short)0x0000);
    const __half hinf = __ushort_as_half((unsigned short)0x7C00);

    int j = W * ll;
    if (j > JC) j = JC;                        // duplicate work, min-safe
    const int e = j >> 1;

    __half2 A[NA], I[NA], E[NA + 1], O[NA + 1];
    float2  f[NA];
    #pragma unroll
    for (int n = 0; n < NA; n++) {
        I[n] = __halves2half2((j + 2 * n     < TW) ? hz : hinf,
                              (j + 2 * n + 1 < TW) ? hz : hinf);
        A[n] = I[n];
        f[n] = make_float2(0.f, 0.f);
    }
    #pragma unroll
    for (int n = 0; n <= NA; n++) { E[n] = she[e + n]; O[n] = sho[e + n]; }

    int h = 0;
    #pragma unroll 1
    for (int hb = 0; hb < NB; hb++) {
        #pragma unroll
        for (int hh = 0; hh < 8; hh++) {
            const uint2 wv = *reinterpret_cast<const uint2*>(swh + 2 * (h + hh));
            const __half2 w0 = *reinterpret_cast<const __half2*>(&wv.x);
            const __half2 w1 = *reinterpret_cast<const __half2*>(&wv.y);
            #pragma unroll
            for (int n = 0; n < NA; n++) {
                A[n] = __hadd2(A[n], __habs2(__hsub2(E[n], w0)));
                A[n] = __hadd2(A[n], __habs2(__hsub2(O[n], w1)));
            }
            #pragma unroll
            for (int n = 0; n < NA; n++) { E[n] = E[n + 1]; O[n] = O[n + 1]; }
            const int idx = e + h + hh + NA + 1;
            E[NA] = she[idx];
            O[NA] = sho[idx];
        }
        h += 8;
        #pragma unroll
        for (int n = 0; n < NA; n++) {         // chunk flush to fp32
            const float2 t = __half22float2(A[n]);
            f[n].x += t.x; f[n].y += t.y;
            A[n] = I[n];
        }
    }
    #pragma unroll
    for (int hh = 0; hh < HREM; hh++) {        // tail h-steps (< 8)
        const uint2 wv = *reinterpret_cast<const uint2*>(swh + 2 * (h + hh));
        const __half2 w0 = *reinterpret_cast<const __half2*>(&wv.x);
        const __half2 w1 = *reinterpret_cast<const __half2*>(&wv.y);
        #pragma unroll
        for (int n = 0; n < NA; n++) {
            A[n] = __hadd2(A[n], __habs2(__hsub2(E[n], w0)));
            A[n] = __hadd2(A[n], __habs2(__hsub2(O[n], w1)));
        }
        #pragma unroll
        for (int n = 0; n < NA; n++) { E[n] = E[n + 1]; O[n] = O[n + 1]; }
        const int idx = e + h + hh + NA + 1;
        E[NA] = she[idx];
        O[NA] = sho[idx];
    }
    if (L & 1) {                               // last even step l = L-1
        const __half2 w0 = swh[L - 1];
        #pragma unroll
        for (int n = 0; n < NA; n++)
            A[n] = __hadd2(A[n], __habs2(__hsub2(E[n], w0)));
    }

    float mn = CUDART_INF_F;
    #pragma unroll
    for (int n = 0; n < NA; n++) {             // final flush + lane min
        const float2 t = __half22float2(A[n]);
        f[n].x += t.x; f[n].y += t.y;
        mn = fminf(mn, fminf(f[n].x, f[n].y));
    }
    #pragma unroll
    for (int o = 16; o > 0; o >>= 1)
        mn = fminf(mn, __shfl_xor_sync(0xffffffffu, mn, o));
    if (ll == 0) atomicMin(sminp, __float_as_uint(mn));   // d>=0: bits monotone
}

// ---------------------------------------------------------------------------
// Single launch. grid.x = 1120 workers + 21 heads, 128 threads (4 warps).
// Warp wp runs group g = (wp+bid)&3 as ONE wide token:
//   g0: W=10 (31 lanes)  g1: W=10 (27)  g2: W=8 (30)  g3: W=6 (29)
// ---------------------------------------------------------------------------
__global__ __launch_bounds__(128, 7) void fused_kernel(
        const float* __restrict__ x,
        const float* __restrict__ w0,
        const float* __restrict__ w1,
        const float* __restrict__ w2,
        const float* __restrict__ w3,
        const float* __restrict__ Wout,
        float* __restrict__ d_out) {
    const int bid = blockIdx.x;
    const int tid = threadIdx.x;          // 128

    if (bid < NWORKBLK) {
        // ================= WORKER =================
        const int nn = bid % NSH;
        const int bc = bid / NSH;
        const int b  = bc / C;
        const int ch = bc % C;
        const int wp = tid >> 5;             // warp 0..3
        const int ll = tid & 31;

        __shared__ __align__(16) float   sxf[SXN];
        __shared__ __align__(16) __half2 she[PAIRN];
        __shared__ __align__(16) __half2 sho[PAIRN];
        __shared__ __align__(16) __half2 swh[SWH_TOT];
        __shared__ float red[8];
        __shared__ unsigned smin[4];

        // ---- normalization: one pass sum + sumsq over the (b,ch) row ----
        const float* xrow = x + (size_t)b * T * C + ch;   // stride C over t
        float vals[3];
        float s = 0.f, ss = 0.f;
        #pragma unroll
        for (int i = 0; i < 3; i++) {
            int t = tid + i * 128;
            float v = (t < T) ? xrow[(size_t)t * C] : 0.f;
            vals[i] = v;
            s += v;
            ss += v * v;
        }
        #pragma unroll
        for (int o = 16; o > 0; o >>= 1) {
            s  += __shfl_xor_sync(0xffffffffu, s, o);
            ss += __shfl_xor_sync(0xffffffffu, ss, o);
        }
        if (ll == 0) { red[wp] = s; red[4 + wp] = ss; }
        if (tid < 4) smin[tid] = 0x7f800000u;   // +inf bits

        // ---- warp wp converts+stores shapelet row of group wp ----
        {
            int L, goff;
            const float* wg;
            switch (wp) {
                case 0:  L = 34;  goff = 0;   wg = w0; break;
                case 1:  L = 68;  goff = 64;  wg = w1; break;
                case 2:  L = 101; goff = 160; wg = w2; break;
                default: L = 168; goff = 288; wg = w3; break;
            }
            const float* wrow = wg + (size_t)(nn * C + ch) * L;
            for (int i = ll; i < L; i += 32)
                swh[goff + i] = __float2half2_rn(wrow[i]);
        }

        __syncthreads();
        const float stot  = red[0] + red[1] + red[2] + red[3];
        const float sstot = red[4] + red[5] + red[6] + red[7];
        const float mu  = stot * (1.0f / (float)T);
        const float var = (sstot - (float)T * mu * mu) * (1.0f / (float)(T - 1));
        const float inv = 1.0f / (sqrtf(fmaxf(var, 0.f)) + 1e-8f);

        #pragma unroll
        for (int i = 0; i < 3; i++) {
            int t = tid + i * 128;
            if (t < T) sxf[t] = (vals[i] - mu) * inv;
        }
        for (int i = T + tid; i < SXN; i += 128) sxf[i] = 0.f;  // zero pads
        __syncthreads();

        // ---- build fp16 pair arrays ----
        for (int i = tid; i < PAIRN; i += 128) {
            she[i] = __floats2half2_rn(sxf[2 * i],     sxf[2 * i + 1]);
            sho[i] = __floats2half2_rn(sxf[2 * i + 1], sxf[2 * i + 2]);
        }
        __syncthreads();

        // ---- one wide token per warp, g rotated across blocks ----
        switch ((wp + bid) & 3) {
            case 0:  run_wide<34,  5>(she, sho, swh + 0,   ll, &smin[0]); break;
            case 1:  run_wide<68,  5>(she, sho, swh + 64,  ll, &smin[1]); break;
            case 2:  run_wide<101, 4>(she, sho, swh + 160, ll, &smin[2]); break;
            default: run_wide<168, 3>(she, sho, swh + 288, ll, &smin[3]); break;
        }
        __syncthreads();

        if (tid < 4) {                      // one thread per g writes results
            const float dmin = __uint_as_float(smin[tid]) * c_invL[tid];
            const int idx = b * NF + tid * (NSH * C) + nn * C + ch;
            d_out[OFF_DIST + idx] = dmin;
            d_out[OFF_PROB + idx] = expf(-dmin * dmin);   // EPS_GATE = 1
        }
        __syncthreads();
        if (tid == 0) {
            __threadfence();
            atomicAdd(&g_ctr, 1);           // publish this block's 4 results
        }
    } else {
        // ================= HEAD =================
        const int h = bid - NWORKBLK;    // 0..20

        if (tid == 0) {
            while (atomicAdd(&g_ctr, 0) < NWORKBLK) __nanosleep(64);
        }
        __syncthreads();
        __threadfence();                  // acquire published probs

        if (h < 20) {
            // 16 dots per block; warp wp does 4 dots
            const int wp = tid >> 5;
            const int ln = tid & 31;
            const float* probs = d_out + OFF_PROB;
            #pragma unroll
            for (int d = 0; d < 4; d++) {
                const int dot = h * 16 + wp * 4 + d;     // < 320
                const int bb = dot / OUTC;
                const int o  = dot % OUTC;
                const float* p  = probs + bb * NF;
                const float* wv = Wout + o * NF;
                float v = 0.f;
                #pragma unroll
                for (int f = ln; f < NF; f += 32) v += p[f] * wv[f];
                #pragma unroll
                for (int off = 16; off > 0; off >>= 1)
                    v += __shfl_xor_sync(0xffffffffu, v, off);
                if (ln == 0) d_out[OFF_OUT + dot] = v;
            }
        } else {
            // loss = 0.1 * mean|Wout|
            __shared__ float sred[4];
            float v = 0.f;
            #pragma unroll
            for (int i = tid; i < OUTC * NF; i += 128) v += fabsf(Wout[i]);
            #pragma unroll
            for (int off = 16; off > 0; off >>= 1)
                v += __shfl_xor_sync(0xffffffffu, v, off);
            if ((tid & 31) == 0) sred[tid >> 5] = v;
            __syncthreads();
            if (tid == 0) {
                float tot = sred[0] + sred[1] + sred[2] + sred[3];
                d_out[OFF_LOSS] = 0.1f * tot / (float)(OUTC * NF);
            }
        }

        __syncthreads();
        if (tid == 0) {
            int v = atomicAdd(&g_ctr2, 1);
            if (v == NHEAD - 1) {
                // last head block resets counters for the next graph replay
                atomicExch(&g_ctr, 0);
                atomicExch(&g_ctr2, 0);
            }
        }
    }
}

// ---------------------------------------------------------------------------
extern "C" void kernel_launch(void* const* d_in, const int* in_sizes, int n_in,
                              void* d_out, int out_size) {
    const float* x    = (const float*)d_in[0];
    const float* w0   = (const float*)d_in[1];
    const float* w1   = (const float*)d_in[2];
    const float* w2   = (const float*)d_in[3];
    const float* w3   = (const float*)d_in[4];
    const float* Wout = (const float*)d_in[5];
    float* out = (float*)d_out;

    fused_kernel<<<NWORKBLK + NHEAD, 128>>>(x, w0, w1, w2, w3, Wout, out);
}